// round 13
// baseline (speedup 1.0000x reference)
#include <cuda_runtime.h>
#include <cstdint>

// IFS trajectory — R4 structure, 4 blocks/SM (48.5 KB smem), TILE=16 pipeline,
// half-tile staging (8 steps) flushed twice per tile.
// inputs: d_in[0] = coef (BATCH, 12) f32, d_in[1] = h (ITERS, BATCH) f32
// output: (BATCH, ITERS+1, 2) f32
//
// Pipeline per tile of 16 steps (cols shifted: tile t covers steps [16t,16t+16)):
//   prefetch(t+1) -> cp_wait<1> -> __syncthreads -> compute 8 + flush + compute
//   8 + flush -> __syncthreads.
// h ring: NBUF=2, depth-1, prefetch issued BEFORE the wait (R4 order).
// Staging: so[8][258] float2; columns are per-warp, so the intra-tile reuse
// needs only __syncwarp. Flush: quarter-warp writes one row's 8 float2 = 64B.

#define BLOCK 256
#define TILE  16
#define HTILE 8
#define NBUF  2
#define SOROW (BLOCK + 2)

__device__ __forceinline__ void cp_async16(uint32_t saddr, const void* gptr) {
    asm volatile("cp.async.cg.shared.global [%0], [%1], 16;\n"
                 :: "r"(saddr), "l"(gptr));
}
__device__ __forceinline__ void cp_commit() {
    asm volatile("cp.async.commit_group;\n");
}
template <int N>
__device__ __forceinline__ void cp_wait() {
    asm volatile("cp.async.wait_group %0;\n" :: "n"(N));
}

__global__ __launch_bounds__(BLOCK, 4) void ifs_traj_kernel(
    const float* __restrict__ coef,
    const float* __restrict__ h,
    float2* __restrict__ out,
    int batch, int iters)
{
    __shared__ __align__(16) float sh[NBUF][TILE][BLOCK];  // 32 KB
    __shared__ float2 so[HTILE][SOROW];                     // ~16.1 KB

    const int tid  = threadIdx.x;
    const int warp = tid >> 5;
    const int lane = tid & 31;
    const int block_b0 = blockIdx.x * BLOCK;
    const int b = block_b0 + tid;
    const bool active = (b < batch);
    const int stride = iters + 1;
    const int nfull  = iters / TILE;

    // ---- per-element setup ----
    float A0=0,A1=0,A2=0,A3=0,A4=0,A5=0,B0=0,B1=0,B2=0,B3=0,B4=0,B5=0,p=0;
    if (active) {
        const float4* c4 = reinterpret_cast<const float4*>(coef + (size_t)b * 12);
        float4 ca = c4[0], cb = c4[1], cc = c4[2];
        A0=ca.x; A1=ca.y; A2=ca.z; A3=ca.w; A4=cb.x; A5=cb.y;
        B0=cb.z; B1=cb.w; B2=cc.x; B3=cc.y; B4=cc.z; B5=cc.w;
        float j0 = fabsf(A0*A3 - A1*A2);
        float j1 = fabsf(B0*B3 - B1*B2);
        p = j0 / (j0 + j1);
        out[(size_t)b * stride] = make_float2(0.05f, 0.05f);  // initial point
    }
    float x = 0.05f, y = 0.05f;

    // ---- h-tile prefetch: 1024 float4 chunks / block, 4 per thread ----
    const uint32_t sh_base = (uint32_t)__cvta_generic_to_shared(&sh[0][0][0]);
    auto prefetch = [&](int tile, int buf) {
        const float* gbase = h + (size_t)(tile * TILE) * batch + block_b0;
        const uint32_t sbuf = sh_base + (uint32_t)(buf * TILE * BLOCK * 4);
        #pragma unroll
        for (int i = 0; i < 4; ++i) {
            int flat = tid + i * BLOCK;
            int row  = flat >> 6;              // 0..15 (64 chunks per row)
            int gb   = (flat & 63) << 2;       // float col, 16B aligned
            if (block_b0 + gb < batch)         // batch % 4 == 0 assumed
                cp_async16(sbuf + (uint32_t)((row * BLOCK + gb) << 2),
                           gbase + (size_t)row * batch + gb);
        }
        cp_commit();
    };

    if (nfull > 0) prefetch(0, 0);

    const int q    = lane >> 3;          // quarter-warp group 0..3
    const int ttf  = lane & 7;           // time index for flush
    const int wcol = warp * 32 + q;      // staging column base

    // flush one staged half-tile; col0 = first global output column
    auto flush = [&](int col0) {
        if (block_b0 + wcol < batch) {   // per-quarter-warp row-group check
            float2* obase = out + (size_t)(block_b0 + wcol) * stride + col0 + ttf;
            #pragma unroll
            for (int k = 0; k < 8; ++k)
                if (block_b0 + wcol + 4 * k < batch)
                    obase[(size_t)(4 * k) * stride] = so[ttf][wcol + 4 * k];
        }
    };

    for (int tile = 0; tile < nfull; ++tile) {
        const int t0  = tile * TILE;
        const int buf = tile & 1;

        if (tile + 1 < nfull) {
            prefetch(tile + 1, buf ^ 1);
            cp_wait<1>();
        } else {
            cp_wait<0>();
        }
        __syncthreads();                  // h tile `tile` visible

        // ---- first half: steps t0..t0+7 ----
        if (active) {
            #pragma unroll
            for (int j = 0; j < HTILE; ++j) {
                float ht = sh[buf][j][tid];
                float xA = fmaf(A0, x, fmaf(A1, y, A4));
                float yA = fmaf(A2, x, fmaf(A3, y, A5));
                float xB = fmaf(B0, x, fmaf(B1, y, B4));
                float yB = fmaf(B2, x, fmaf(B3, y, B5));
                bool m = ht > p;
                x = m ? xB : xA;
                y = m ? yB : yA;
                so[j][tid] = make_float2(x, y);
            }
        }
        __syncwarp();
        flush(1 + t0);                    // output cols 1+t0 .. 1+t0+7
        __syncwarp();

        // ---- second half: steps t0+8..t0+15 ----
        if (active) {
            #pragma unroll
            for (int j = 0; j < HTILE; ++j) {
                float ht = sh[buf][HTILE + j][tid];
                float xA = fmaf(A0, x, fmaf(A1, y, A4));
                float yA = fmaf(A2, x, fmaf(A3, y, A5));
                float xB = fmaf(B0, x, fmaf(B1, y, B4));
                float yB = fmaf(B2, x, fmaf(B3, y, B5));
                bool m = ht > p;
                x = m ? xB : xA;
                y = m ? yB : yA;
                so[j][tid] = make_float2(x, y);
            }
        }
        __syncwarp();
        flush(1 + t0 + HTILE);
        __syncthreads();                  // all reads of sh[buf] done
    }

    // ---- tail: remaining iters % TILE steps ----
    const int trem = iters - nfull * TILE;
    if (trem > 0) {
        const int t0 = nfull * TILE;
        if (active) {
            for (int j = 0; j < trem; ++j) {
                float ht = __ldg(h + (size_t)(t0 + j) * batch + b);
                float xA = fmaf(A0, x, fmaf(A1, y, A4));
                float yA = fmaf(A2, x, fmaf(A3, y, A5));
                float xB = fmaf(B0, x, fmaf(B1, y, B4));
                float yB = fmaf(B2, x, fmaf(B3, y, B5));
                bool m = ht > p;
                x = m ? xB : xA;
                y = m ? yB : yA;
                if (j < HTILE) so[j][tid] = make_float2(x, y);
                else           out[(size_t)b * stride + 1 + t0 + j] = make_float2(x, y);
            }
        }
        __syncwarp();
        if (ttf < trem && block_b0 + wcol < batch) {
            float2* obase = out + (size_t)(block_b0 + wcol) * stride + 1 + t0 + ttf;
            #pragma unroll
            for (int k = 0; k < 8; ++k)
                if (block_b0 + wcol + 4 * k < batch)
                    obase[(size_t)(4 * k) * stride] = so[ttf][wcol + 4 * k];
        }
    }
}

extern "C" void kernel_launch(void* const* d_in, const int* in_sizes, int n_in,
                              void* d_out, int out_size) {
    const float* coef = (const float*)d_in[0];
    const float* h    = (const float*)d_in[1];
    float2* out       = (float2*)d_out;

    int batch = in_sizes[0] / 12;
    int iters = in_sizes[1] / batch;

    int blocks = (batch + BLOCK - 1) / BLOCK;
    ifs_traj_kernel<<<blocks, BLOCK>>>(coef, h, out, batch, iters);
}

// round 14
// speedup vs baseline: 1.1986x; 1.1986x over previous
#include <cuda_runtime.h>
#include <cstdint>

// IFS trajectory kernel — the proven R4 structure (block-wide TILE=16 h tiles,
// cp.async double-buffer, 128B half-warp-row flush), with ONE change: the
// per-tile order is  cp_wait -> __syncthreads -> prefetch(next), which lets a
// single block barrier per tile order both h-tile visibility AND ring reuse
// (prefetch(t+1) overwrites buf^1 only after barrier #t; all reads of buf^1
// happened in iteration t-1, before that barrier).
//
// inputs: d_in[0] = coef (BATCH, 12) f32, d_in[1] = h (ITERS, BATCH) f32
// output: (BATCH, ITERS+1, 2) f32

#define BLOCK 256
#define TILE  16
#define WARPS (BLOCK / 32)
#define NBUF  2

__device__ __forceinline__ void cp_async16(uint32_t saddr, const void* gptr) {
    asm volatile("cp.async.cg.shared.global [%0], [%1], 16;\n"
                 :: "r"(saddr), "l"(gptr));
}
__device__ __forceinline__ void cp_commit() {
    asm volatile("cp.async.commit_group;\n");
}
template <int N>
__device__ __forceinline__ void cp_wait() {
    asm volatile("cp.async.wait_group %0;\n" :: "n"(N));
}

__global__ __launch_bounds__(BLOCK, 3) void ifs_traj_kernel(
    const float* __restrict__ coef,
    const float* __restrict__ h,
    float2* __restrict__ out,
    int batch, int iters)
{
    __shared__ __align__(16) float sh[NBUF][TILE][BLOCK];   // 32 KB h ring
    __shared__ float2 so[WARPS][32][TILE + 1];              // ~35 KB staging

    const int tid  = threadIdx.x;
    const int warp = tid >> 5;
    const int lane = tid & 31;
    const int block_b0 = blockIdx.x * BLOCK;
    const int b = block_b0 + tid;
    const bool active = (b < batch);
    const int stride = iters + 1;
    const int nfull  = iters / TILE;

    // ---- per-element setup ----
    float A0=0,A1=0,A2=0,A3=0,A4=0,A5=0,B0=0,B1=0,B2=0,B3=0,B4=0,B5=0,p=0;
    if (active) {
        const float4* c4 = reinterpret_cast<const float4*>(coef + (size_t)b * 12);
        float4 ca = c4[0], cb = c4[1], cc = c4[2];
        A0=ca.x; A1=ca.y; A2=ca.z; A3=ca.w; A4=cb.x; A5=cb.y;
        B0=cb.z; B1=cb.w; B2=cc.x; B3=cc.y; B4=cc.z; B5=cc.w;
        float j0 = fabsf(A0*A3 - A1*A2);
        float j1 = fabsf(B0*B3 - B1*B2);
        p = j0 / (j0 + j1);
        out[(size_t)b * stride] = make_float2(0.05f, 0.05f);   // initial point
    }
    float x = 0.05f, y = 0.05f;

    // ---- h-tile prefetch: 1024 float4 chunks / block, 4 per thread ----
    const uint32_t sh_base = (uint32_t)__cvta_generic_to_shared(&sh[0][0][0]);
    auto prefetch = [&](int tile, int buf) {
        const float* gbase = h + (size_t)(tile * TILE) * batch + block_b0;
        const uint32_t sbuf = sh_base + (uint32_t)(buf * TILE * BLOCK * 4);
        #pragma unroll
        for (int i = 0; i < 4; ++i) {
            int flat = tid + i * BLOCK;
            int row  = flat >> 6;              // 0..15 (64 chunks per row)
            int gb   = (flat & 63) << 2;       // float col, 16B aligned
            if (block_b0 + gb < batch)         // batch % 4 == 0 assumed
                cp_async16(sbuf + (uint32_t)((row * BLOCK + gb) << 2),
                           gbase + (size_t)row * batch + gb);
        }
        cp_commit();
    };

    if (nfull > 0) prefetch(0, 0);

    const int rhalf = lane >> 4;     // half-warp row group
    const int ttf   = lane & 15;     // time index for flush

    for (int tile = 0; tile < nfull; ++tile) {
        const int t0  = tile * TILE;
        const int buf = tile & 1;

        cp_wait<0>();                // the one outstanding group (tile t) done
        __syncthreads();             // h tile visible; reads of buf^1 all done
        if (tile + 1 < nfull)
            prefetch(tile + 1, buf ^ 1);   // safe: post-barrier overwrite

        // ---- recurrence: 16 steps from smem, stage to per-warp slice ----
        if (active) {
            #pragma unroll
            for (int tt = 0; tt < TILE; ++tt) {
                float ht = sh[buf][tt][tid];
                float xA = fmaf(A0, x, fmaf(A1, y, A4));
                float yA = fmaf(A2, x, fmaf(A3, y, A5));
                float xB = fmaf(B0, x, fmaf(B1, y, B4));
                float yB = fmaf(B2, x, fmaf(B3, y, B5));
                bool m = ht > p;
                x = m ? xB : xA;
                y = m ? yB : yA;
                so[warp][lane][tt] = make_float2(x, y);
            }
        }
        __syncwarp();

        // ---- flush: half-warp writes one row's 16 float2 = 128B ----
        {
            const int warp_b0 = block_b0 + warp * 32;
            #pragma unroll
            for (int k = 0; k < 16; ++k) {
                int bl = 2 * k + rhalf;
                int bg = warp_b0 + bl;
                if (bg < batch)
                    out[(size_t)bg * stride + 1 + t0 + ttf] = so[warp][bl][ttf];
            }
        }
        // no trailing barrier: next iteration's __syncthreads orders
        // both so-reuse and sh-ring reuse.
    }

    // ---- tail tile (iters % TILE steps) ----
    const int trem = iters - nfull * TILE;
    if (trem > 0) {
        const int t0 = nfull * TILE;
        __syncwarp();                      // flush reads of so complete (warp-local)
        if (active) {
            for (int tt = 0; tt < trem; ++tt) {
                float ht = __ldg(h + (size_t)(t0 + tt) * batch + b);
                float xA = fmaf(A0, x, fmaf(A1, y, A4));
                float yA = fmaf(A2, x, fmaf(A3, y, A5));
                float xB = fmaf(B0, x, fmaf(B1, y, B4));
                float yB = fmaf(B2, x, fmaf(B3, y, B5));
                bool m = ht > p;
                x = m ? xB : xA;
                y = m ? yB : yA;
                so[warp][lane][tt] = make_float2(x, y);
            }
        }
        __syncwarp();
        {
            const int warp_b0 = block_b0 + warp * 32;
            #pragma unroll
            for (int k = 0; k < 16; ++k) {
                int bl = 2 * k + rhalf;
                int bg = warp_b0 + bl;
                if (bg < batch && ttf < trem)
                    out[(size_t)bg * stride + 1 + t0 + ttf] = so[warp][bl][ttf];
            }
        }
    }
}

extern "C" void kernel_launch(void* const* d_in, const int* in_sizes, int n_in,
                              void* d_out, int out_size) {
    const float* coef = (const float*)d_in[0];
    const float* h    = (const float*)d_in[1];
    float2* out       = (float2*)d_out;

    int batch = in_sizes[0] / 12;
    int iters = in_sizes[1] / batch;

    int blocks = (batch + BLOCK - 1) / BLOCK;
    ifs_traj_kernel<<<blocks, BLOCK>>>(coef, h, out, batch, iters);
}